// round 14
// baseline (speedup 1.0000x reference)
#include <cuda_runtime.h>

// Problem constants (fixed by reference setup_inputs)
#define Bn   32
#define Pn   32
#define Sn   512
#define PSn  (Pn * Sn)            // 16384
#define Ntot (Bn * Pn * PSn)      // 16,777,216 elements per output plane
#define PCHUNK 8                  // p's per block
#define JW     4                  // j's per thread

// Block = 256 threads -> covers 256*JW = 1024 j.
// grid = (PS/1024, Pn/PCHUNK, B) = (16, 4, 32) = 2048 blocks.
//
// Champion structure (round 5/13, 34.9 us) with ONE change: plain write-back
// stores instead of __stcs. In steady-state graph replay the output (201 MB
// per period) must drain through DRAM; write-back lets the period's dirty
// tail (~100 MB fits in the 126 MB L2) drain lazily, overlapped with the next
// replay's prologue, instead of being forced out eagerly by evict-first.

__global__ __launch_bounds__(256, 3)
void mutex_loss_kernel(const float* __restrict__ shape_rlt,
                       const float* __restrict__ trans_rlt,
                       const float* __restrict__ quat_rlt,
                       const float* __restrict__ ioul,
                       const float* __restrict__ coef,
                       float* __restrict__ out)
{
    // Vector-packed per-p params for this batch b:
    //  spA = (r00,r01,r02,r10)  spB = (r11,r12,r20,r21)
    //  spC = (r22, tx, ty, tz)  spD = (sx, sy, sz, iou)
    //  spW = vol*iou
    __shared__ float4 spA[Pn], spB[Pn], spC[Pn], spD[Pn];
    __shared__ float  spW[Pn];

    const int b     = blockIdx.z;
    const int pbase = blockIdx.y * PCHUNK;
    const int tid   = threadIdx.x;

    if (tid < Pn) {
        const int p  = tid;
        const int bp = b * Pn + p;
        float qw = quat_rlt[bp * 4 + 0];
        float qx = quat_rlt[bp * 4 + 1];
        float qy = quat_rlt[bp * 4 + 2];
        float qz = quat_rlt[bp * 4 + 3];
        float inv = rsqrtf(qw * qw + qx * qx + qy * qy + qz * qz);
        qw *= inv; qx *= inv; qy *= inv; qz *= inv;
        float r00 = 1.0f - 2.0f * (qy * qy + qz * qz);
        float r01 = 2.0f * (qx * qy - qw * qz);
        float r02 = 2.0f * (qx * qz + qw * qy);
        float r10 = 2.0f * (qx * qy + qw * qz);
        float r11 = 1.0f - 2.0f * (qx * qx + qz * qz);
        float r12 = 2.0f * (qy * qz - qw * qx);
        float r20 = 2.0f * (qx * qz - qw * qy);
        float r21 = 2.0f * (qy * qz + qw * qx);
        float r22 = 1.0f - 2.0f * (qx * qx + qy * qy);
        float tx = trans_rlt[bp * 3 + 0];
        float ty = trans_rlt[bp * 3 + 1];
        float tz = trans_rlt[bp * 3 + 2];
        float sx = shape_rlt[bp * 3 + 0];
        float sy = shape_rlt[bp * 3 + 1];
        float sz = shape_rlt[bp * 3 + 2];
        float io = ioul[bp];
        spA[p] = make_float4(r00, r01, r02, r10);
        spB[p] = make_float4(r11, r12, r20, r21);
        spC[p] = make_float4(r22, tx, ty, tz);
        spD[p] = make_float4(sx, sy, sz, io);
        spW[p] = sx * sy * sz * io;
    }
    __syncthreads();

    const int j0    = (blockIdx.x * 256 + tid) * JW;
    const int owner = j0 >> 9;            // j / S
    const int s     = j0 & (Sn - 1);      // j % S

    const float w = spW[owner];
    const float4 wvec = make_float4(w, w, w, w);
    const float4 zvec = make_float4(0.0f, 0.0f, 0.0f, 0.0f);

    float* __restrict__ outT = out;
    float* __restrict__ outW = out + (size_t)Ntot;
    float* __restrict__ outG = out + 2 * (size_t)Ntot;
    const int basebj = b * Pn * PSn + j0;

    // ---- Fill the weight and zero planes up-front (no compute deps):
    // fills the store pipe while the tsdf FMA chains below are in flight.
#pragma unroll
    for (int pi = 0; pi < PCHUNK; pi++) {
        const int o = basebj + (pbase + pi) * PSn;
        *reinterpret_cast<float4*>(outW + o) = wvec;
        *reinterpret_cast<float4*>(outG + o) = zvec;
    }

    // ---- Load 4 coef points (12 contiguous floats, 16B-aligned) ----
    const float4* cptr = reinterpret_cast<const float4*>(
        coef + ((size_t)(b * Pn + owner) * Sn + s) * 3);
    float4 c0 = cptr[0];
    float4 c1 = cptr[1];
    float4 c2 = cptr[2];

    // Owner params
    const float4 oA = spA[owner], oB = spB[owner], oC = spC[owner], oD = spD[owner];

    // Build the 4 world-space points: point = R_owner * ((2c-1)*shape) + t
    float px[JW], py[JW], pz[JW];
    {
        float cx[4] = {c0.x, c0.w, c1.z, c2.y};
        float cy[4] = {c0.y, c1.x, c1.w, c2.z};
        float cz[4] = {c0.z, c1.y, c2.x, c2.w};
#pragma unroll
        for (int i = 0; i < JW; i++) {
            float lx = fmaf(cx[i], 2.0f * oD.x, -oD.x);   // (2c-1)*sx
            float ly = fmaf(cy[i], 2.0f * oD.y, -oD.y);
            float lz = fmaf(cz[i], 2.0f * oD.z, -oD.z);
            px[i] = oA.x * lx + oA.y * ly + oA.z * lz + oC.y;
            py[i] = oA.w * lx + oB.x * ly + oB.y * lz + oC.z;
            pz[i] = oB.z * lx + oB.w * ly + oC.x * lz + oC.w;
        }
    }

#pragma unroll
    for (int pi = 0; pi < PCHUNK; pi++) {
        const int p = pbase + pi;
        const float4 A  = spA[p];
        const float4 Bv = spB[p];
        const float4 C  = spC[p];
        const float4 D  = spD[p];
        const float m   = (p == owner) ? 0.0f : D.w;

        float res[JW];
#pragma unroll
        for (int i = 0; i < JW; i++) {
            float dx = px[i] - C.y, dy = py[i] - C.z, dz = pz[i] - C.w;
            // conjugate rotation = R^T * d
            float lx = A.x * dx + A.w * dy + Bv.z * dz;
            float ly = A.y * dx + Bv.x * dy + Bv.w * dz;
            float lz = A.z * dx + Bv.y * dy + C.x  * dz;
            float ex = fmaxf(D.x - fabsf(lx), 0.0f);
            float ey = fmaxf(D.y - fabsf(ly), 0.0f);
            float ez = fmaxf(D.z - fabsf(lz), 0.0f);
            res[i] = (ex * ex + ey * ey + ez * ez) * m;
        }

        *reinterpret_cast<float4*>(outT + basebj + p * PSn) =
            make_float4(res[0], res[1], res[2], res[3]);
    }
}

extern "C" void kernel_launch(void* const* d_in, const int* in_sizes, int n_in,
                              void* d_out, int out_size)
{
    const float* shape_rlt = (const float*)d_in[0];
    const float* trans_rlt = (const float*)d_in[1];
    const float* quat_rlt  = (const float*)d_in[2];
    const float* ioulist   = (const float*)d_in[3];
    const float* coef      = (const float*)d_in[4];
    float* out = (float*)d_out;

    dim3 grid(PSn / (256 * JW), Pn / PCHUNK, Bn);   // (16, 4, 32) = 2048 blocks
    mutex_loss_kernel<<<grid, 256>>>(shape_rlt, trans_rlt, quat_rlt, ioulist, coef, out);
}

// round 15
// speedup vs baseline: 1.1175x; 1.1175x over previous
#include <cuda_runtime.h>

// Problem constants (fixed by reference setup_inputs)
#define Bn   32
#define Pn   32
#define Sn   512
#define PSn  (Pn * Sn)            // 16384
#define Ntot (Bn * Pn * PSn)      // 16,777,216 elements per output plane
#define PCHUNK 8                  // p's per block
#define JW     4                  // j's per thread

// Block = 256 threads -> covers 256*JW = 1024 j.
// grid = (PS/1024, Pn/PCHUNK, B) = (16, 4, 32) = 2048 blocks.
//
// FINAL champion configuration (rounds 5/13: 34.9 us, rel_err 5.2e-7).
// This kernel sits at the steady-state DRAM write wall: ~207 MB committed per
// graph-replay period = ~5.9 TB/s sustained on a ~97%-write mix. Exhaustively
// measured alternatives, all flat or regressing:
//   occupancy/grid/block sweeps (22-60%, 512-3072 blocks)   -> flat 35+-2
//   JW=8 in three variants                                   -> spills, 39-55
//   v8.f32 stores (cracked to 2 LSU wavefronts)              -> 39
//   parallel memset branch (no overlap at full residency)    -> 37.3
//   compute/fill block specialization                        -> 36.2
//   L2 evict_last residency pinning                          -> 41.1
//   plain write-back stores (dirty-tail collides w/ next rep)-> 38.9
// __stcs (evict-first) is load-bearing: it keeps L2 clean so each period's
// store stream allocates without synchronous write-back evictions.

__global__ __launch_bounds__(256, 3)
void mutex_loss_kernel(const float* __restrict__ shape_rlt,
                       const float* __restrict__ trans_rlt,
                       const float* __restrict__ quat_rlt,
                       const float* __restrict__ ioul,
                       const float* __restrict__ coef,
                       float* __restrict__ out)
{
    // Vector-packed per-p params for this batch b:
    //  spA = (r00,r01,r02,r10)  spB = (r11,r12,r20,r21)
    //  spC = (r22, tx, ty, tz)  spD = (sx, sy, sz, iou)
    //  spW = vol*iou
    __shared__ float4 spA[Pn], spB[Pn], spC[Pn], spD[Pn];
    __shared__ float  spW[Pn];

    const int b     = blockIdx.z;
    const int pbase = blockIdx.y * PCHUNK;
    const int tid   = threadIdx.x;

    if (tid < Pn) {
        const int p  = tid;
        const int bp = b * Pn + p;
        float qw = quat_rlt[bp * 4 + 0];
        float qx = quat_rlt[bp * 4 + 1];
        float qy = quat_rlt[bp * 4 + 2];
        float qz = quat_rlt[bp * 4 + 3];
        float inv = rsqrtf(qw * qw + qx * qx + qy * qy + qz * qz);
        qw *= inv; qx *= inv; qy *= inv; qz *= inv;
        float r00 = 1.0f - 2.0f * (qy * qy + qz * qz);
        float r01 = 2.0f * (qx * qy - qw * qz);
        float r02 = 2.0f * (qx * qz + qw * qy);
        float r10 = 2.0f * (qx * qy + qw * qz);
        float r11 = 1.0f - 2.0f * (qx * qx + qz * qz);
        float r12 = 2.0f * (qy * qz - qw * qx);
        float r20 = 2.0f * (qx * qz - qw * qy);
        float r21 = 2.0f * (qy * qz + qw * qx);
        float r22 = 1.0f - 2.0f * (qx * qx + qy * qy);
        float tx = trans_rlt[bp * 3 + 0];
        float ty = trans_rlt[bp * 3 + 1];
        float tz = trans_rlt[bp * 3 + 2];
        float sx = shape_rlt[bp * 3 + 0];
        float sy = shape_rlt[bp * 3 + 1];
        float sz = shape_rlt[bp * 3 + 2];
        float io = ioul[bp];
        spA[p] = make_float4(r00, r01, r02, r10);
        spB[p] = make_float4(r11, r12, r20, r21);
        spC[p] = make_float4(r22, tx, ty, tz);
        spD[p] = make_float4(sx, sy, sz, io);
        spW[p] = sx * sy * sz * io;
    }
    __syncthreads();

    const int j0    = (blockIdx.x * 256 + tid) * JW;
    const int owner = j0 >> 9;            // j / S
    const int s     = j0 & (Sn - 1);      // j % S

    const float w = spW[owner];
    const float4 wvec = make_float4(w, w, w, w);
    const float4 zvec = make_float4(0.0f, 0.0f, 0.0f, 0.0f);

    float* __restrict__ outT = out;
    float* __restrict__ outW = out + (size_t)Ntot;
    float* __restrict__ outG = out + 2 * (size_t)Ntot;
    const int basebj = b * Pn * PSn + j0;

    // ---- Fill the weight and zero planes up-front (no compute deps):
    // fills the store pipe while the tsdf FMA chains below are in flight.
#pragma unroll
    for (int pi = 0; pi < PCHUNK; pi++) {
        const int o = basebj + (pbase + pi) * PSn;
        __stcs(reinterpret_cast<float4*>(outW + o), wvec);
        __stcs(reinterpret_cast<float4*>(outG + o), zvec);
    }

    // ---- Load 4 coef points (12 contiguous floats, 16B-aligned) ----
    const float4* cptr = reinterpret_cast<const float4*>(
        coef + ((size_t)(b * Pn + owner) * Sn + s) * 3);
    float4 c0 = cptr[0];
    float4 c1 = cptr[1];
    float4 c2 = cptr[2];

    // Owner params
    const float4 oA = spA[owner], oB = spB[owner], oC = spC[owner], oD = spD[owner];

    // Build the 4 world-space points: point = R_owner * ((2c-1)*shape) + t
    float px[JW], py[JW], pz[JW];
    {
        float cx[4] = {c0.x, c0.w, c1.z, c2.y};
        float cy[4] = {c0.y, c1.x, c1.w, c2.z};
        float cz[4] = {c0.z, c1.y, c2.x, c2.w};
#pragma unroll
        for (int i = 0; i < JW; i++) {
            float lx = fmaf(cx[i], 2.0f * oD.x, -oD.x);   // (2c-1)*sx
            float ly = fmaf(cy[i], 2.0f * oD.y, -oD.y);
            float lz = fmaf(cz[i], 2.0f * oD.z, -oD.z);
            px[i] = oA.x * lx + oA.y * ly + oA.z * lz + oC.y;
            py[i] = oA.w * lx + oB.x * ly + oB.y * lz + oC.z;
            pz[i] = oB.z * lx + oB.w * ly + oC.x * lz + oC.w;
        }
    }

#pragma unroll
    for (int pi = 0; pi < PCHUNK; pi++) {
        const int p = pbase + pi;
        const float4 A  = spA[p];
        const float4 Bv = spB[p];
        const float4 C  = spC[p];
        const float4 D  = spD[p];
        const float m   = (p == owner) ? 0.0f : D.w;

        float res[JW];
#pragma unroll
        for (int i = 0; i < JW; i++) {
            float dx = px[i] - C.y, dy = py[i] - C.z, dz = pz[i] - C.w;
            // conjugate rotation = R^T * d
            float lx = A.x * dx + A.w * dy + Bv.z * dz;
            float ly = A.y * dx + Bv.x * dy + Bv.w * dz;
            float lz = A.z * dx + Bv.y * dy + C.x  * dz;
            float ex = fmaxf(D.x - fabsf(lx), 0.0f);
            float ey = fmaxf(D.y - fabsf(ly), 0.0f);
            float ez = fmaxf(D.z - fabsf(lz), 0.0f);
            res[i] = (ex * ex + ey * ey + ez * ez) * m;
        }

        __stcs(reinterpret_cast<float4*>(outT + basebj + p * PSn),
               make_float4(res[0], res[1], res[2], res[3]));
    }
}

extern "C" void kernel_launch(void* const* d_in, const int* in_sizes, int n_in,
                              void* d_out, int out_size)
{
    const float* shape_rlt = (const float*)d_in[0];
    const float* trans_rlt = (const float*)d_in[1];
    const float* quat_rlt  = (const float*)d_in[2];
    const float* ioulist   = (const float*)d_in[3];
    const float* coef      = (const float*)d_in[4];
    float* out = (float*)d_out;

    dim3 grid(PSn / (256 * JW), Pn / PCHUNK, Bn);   // (16, 4, 32) = 2048 blocks
    mutex_loss_kernel<<<grid, 256>>>(shape_rlt, trans_rlt, quat_rlt, ioulist, coef, out);
}